// round 1
// baseline (speedup 1.0000x reference)
#include <cuda_runtime.h>
#include <cstdint>

#define Bsz 32
#define Lsz 512
#define Csz 512
#define Hsz 8
#define Dh  64
#define Msz (Bsz*Lsz)   // 16384

// Scratch (device globals: allocation-free contract)
__device__ float g_q[Bsz*Hsz*Lsz*Dh];
__device__ float g_k[Bsz*Hsz*Lsz*Dh];
__device__ float g_v[Bsz*Hsz*Lsz*Dh];
__device__ float g_o[Msz*Csz];

__device__ __forceinline__ float f2tf(float f){
    unsigned u; asm("cvt.rna.tf32.f32 %0, %1;" : "=r"(u) : "f"(f));
    return __uint_as_float(u);
}
__device__ __forceinline__ float4 tf4(float4 v){
    v.x = f2tf(v.x); v.y = f2tf(v.y); v.z = f2tf(v.z); v.w = f2tf(v.w);
    return v;
}
__device__ __forceinline__ void mma8(float* c, const unsigned* a, const unsigned* b){
    asm volatile("mma.sync.aligned.m16n8k8.row.col.f32.tf32.tf32.f32 "
        "{%0,%1,%2,%3}, {%4,%5,%6,%7}, {%8,%9}, {%0,%1,%2,%3};"
        : "+f"(c[0]), "+f"(c[1]), "+f"(c[2]), "+f"(c[3])
        : "r"(a[0]), "r"(a[1]), "r"(a[2]), "r"(a[3]), "r"(b[0]), "r"(b[1]));
}

// ---------------------------------------------------------------------------
// Kernel 1: QKV projection.  y = x @ W^T for W in {wq,wk,wv}.
// CTA tile 128(M) x 64(N), BK=32, 8 warps (4x2 warp grid, 32x32 warp tiles).
// Output written directly in (B,H,L,Dh) layout.
// ---------------------------------------------------------------------------
__global__ void __launch_bounds__(256) qkv_kernel(
    const float* __restrict__ x,
    const float* __restrict__ wq,
    const float* __restrict__ wk,
    const float* __restrict__ wv)
{
    __shared__ float As[128][36];
    __shared__ float Bs[64][36];

    const int mt = blockIdx.x;           // 0..127
    const int nt = blockIdx.y;           // 0..23
    const int which = nt >> 3;
    const int n0 = (nt & 7) * 64;
    const float* w   = (which == 0) ? wq  : (which == 1) ? wk  : wv;
    float*       dst = (which == 0) ? g_q : (which == 1) ? g_k : g_v;
    const int m0 = mt * 128;

    const int t = threadIdx.x;
    const int lane = t & 31, warp = t >> 5;
    const int wr = warp >> 1, wc = warp & 1;
    const int g = lane >> 2, c4 = lane & 3;

    float acc[2][4][4];
#pragma unroll
    for (int mi = 0; mi < 2; mi++)
#pragma unroll
        for (int ni = 0; ni < 4; ni++)
#pragma unroll
            for (int e = 0; e < 4; e++) acc[mi][ni][e] = 0.f;

    for (int k0 = 0; k0 < Csz; k0 += 32) {
        // fill As (128x32) and Bs (64x32) as tf32-rounded floats
#pragma unroll
        for (int i = 0; i < 4; i++) {
            int f = t + i * 256;
            int r = f >> 3, cc = (f & 7) * 4;
            float4 v4 = tf4(*(const float4*)(x + (size_t)(m0 + r) * Csz + k0 + cc));
            *(float4*)(&As[r][cc]) = v4;
        }
#pragma unroll
        for (int i = 0; i < 2; i++) {
            int f = t + i * 256;
            int r = f >> 3, cc = (f & 7) * 4;
            float4 v4 = tf4(*(const float4*)(w + (size_t)(n0 + r) * Csz + k0 + cc));
            *(float4*)(&Bs[r][cc]) = v4;
        }
        __syncthreads();

#pragma unroll
        for (int ks = 0; ks < 32; ks += 8) {
            unsigned a[2][4], b[4][2];
#pragma unroll
            for (int mi = 0; mi < 2; mi++) {
                const float* ap = &As[wr*32 + mi*16 + g][ks + c4];
                a[mi][0] = __float_as_uint(ap[0]);
                a[mi][1] = __float_as_uint(ap[8*36]);
                a[mi][2] = __float_as_uint(ap[4]);
                a[mi][3] = __float_as_uint(ap[8*36 + 4]);
            }
#pragma unroll
            for (int ni = 0; ni < 4; ni++) {
                const float* bp = &Bs[wc*32 + ni*8 + g][ks + c4];
                b[ni][0] = __float_as_uint(bp[0]);
                b[ni][1] = __float_as_uint(bp[4]);
            }
#pragma unroll
            for (int mi = 0; mi < 2; mi++)
#pragma unroll
                for (int ni = 0; ni < 4; ni++)
                    mma8(acc[mi][ni], a[mi], b[ni]);
        }
        __syncthreads();
    }

    // epilogue: n-tile is 64-wide and 64-aligned -> single head per CTA
    const int h = n0 >> 6;
#pragma unroll
    for (int mi = 0; mi < 2; mi++) {
        int row = m0 + wr*32 + mi*16 + g;
        int bb = row >> 9, ll = row & 511;
#pragma unroll
        for (int ni = 0; ni < 4; ni++) {
            int col = wc*32 + ni*8 + 2*c4;     // d within head
            float* p = dst + (((size_t)(bb*Hsz + h) * Lsz + ll) * Dh + col);
            p[0] = acc[mi][ni][0]; p[1] = acc[mi][ni][1];
            p[8*Dh] = acc[mi][ni][2]; p[8*Dh + 1] = acc[mi][ni][3];
        }
    }
}

// ---------------------------------------------------------------------------
// Kernel 2: fused attention per (b,h,q-tile of 128).
// Pass 1: l[q] = sum_k exp(s).  Pass 2: P' = exp(s)/l + bias; O = P' @ V.
// No max-subtraction needed (|s| < ~0.5).  Bias folded post-softmax exactly.
// ---------------------------------------------------------------------------
__global__ void __launch_bounds__(256) attn_kernel(const float* __restrict__ bias_table)
{
    extern __shared__ float smf[];
    float* Qs     = smf;            // [128][68]
    float* Ks     = smf + 8704;     // [64][68]
    float* Vs     = smf + 13056;    // [64][72]  (stride 72: conflict-free B-frag)
    float* Ps     = smf + 17664;    // [128][68]
    float* bias_s = smf + 26368;    // [1024]
    float* l_s    = smf + 27392;    // [128]
    float* lsum   = smf + 27520;    // [2][128]

    const int qt = blockIdx.x;          // 0..3
    const int bh = blockIdx.y;          // 0..255
    const int h = bh & (Hsz - 1);
    const int q0 = qt * 128;
    const int t = threadIdx.x;
    const int lane = t & 31, warp = t >> 5;
    const int wr = warp >> 1, wc = warp & 1;
    const int g = lane >> 2, c4 = lane & 3;

    const float* qg = g_q + (size_t)bh * Lsz * Dh;
    const float* kg = g_k + (size_t)bh * Lsz * Dh;
    const float* vg = g_v + (size_t)bh * Lsz * Dh;
    const float scale = 0.04419417382415922f;   // 512^-0.5

    // Q tile (held for whole CTA lifetime)
#pragma unroll
    for (int i = 0; i < 8; i++) {
        int f = t + i * 256;
        int r = f >> 4, cc = (f & 15) * 4;
        *(float4*)(Qs + r*68 + cc) = tf4(*(const float4*)(qg + (size_t)(q0 + r)*Dh + cc));
    }
    for (int i = t; i < 2*Lsz - 1; i += 256) bias_s[i] = bias_table[i*Hsz + h];
    if (t < 128) l_s[t] = 0.f;
    __syncthreads();

    // ---------------- pass 1: row sums ----------------
    for (int kk = 0; kk < 8; kk++) {
#pragma unroll
        for (int i = 0; i < 4; i++) {
            int f = t + i * 256;
            int r = f >> 4, cc = (f & 15) * 4;
            *(float4*)(Ks + r*68 + cc) = tf4(*(const float4*)(kg + (size_t)(kk*64 + r)*Dh + cc));
        }
        __syncthreads();

        float acc[2][4][4];
#pragma unroll
        for (int mi = 0; mi < 2; mi++)
#pragma unroll
            for (int ni = 0; ni < 4; ni++)
#pragma unroll
                for (int e = 0; e < 4; e++) acc[mi][ni][e] = 0.f;

#pragma unroll
        for (int ks = 0; ks < 64; ks += 8) {
            unsigned a[2][4], b[4][2];
#pragma unroll
            for (int mi = 0; mi < 2; mi++) {
                const float* ap = Qs + (wr*32 + mi*16 + g)*68 + ks + c4;
                a[mi][0] = __float_as_uint(ap[0]);
                a[mi][1] = __float_as_uint(ap[8*68]);
                a[mi][2] = __float_as_uint(ap[4]);
                a[mi][3] = __float_as_uint(ap[8*68 + 4]);
            }
#pragma unroll
            for (int ni = 0; ni < 4; ni++) {
                const float* bp = Ks + (wc*32 + ni*8 + g)*68 + ks + c4;
                b[ni][0] = __float_as_uint(bp[0]);
                b[ni][1] = __float_as_uint(bp[4]);
            }
#pragma unroll
            for (int mi = 0; mi < 2; mi++)
#pragma unroll
                for (int ni = 0; ni < 4; ni++)
                    mma8(acc[mi][ni], a[mi], b[ni]);
        }

#pragma unroll
        for (int mi = 0; mi < 2; mi++) {
            float s0 = 0.f, s1 = 0.f;
#pragma unroll
            for (int ni = 0; ni < 4; ni++) {
                s0 += __expf(acc[mi][ni][0]*scale) + __expf(acc[mi][ni][1]*scale);
                s1 += __expf(acc[mi][ni][2]*scale) + __expf(acc[mi][ni][3]*scale);
            }
            s0 += __shfl_xor_sync(0xffffffffu, s0, 1);
            s0 += __shfl_xor_sync(0xffffffffu, s0, 2);
            s1 += __shfl_xor_sync(0xffffffffu, s1, 1);
            s1 += __shfl_xor_sync(0xffffffffu, s1, 2);
            if (c4 == 0) {
                lsum[wc*128 + wr*32 + mi*16 + g]     = s0;
                lsum[wc*128 + wr*32 + mi*16 + g + 8] = s1;
            }
        }
        __syncthreads();
        if (t < 128) l_s[t] += lsum[t] + lsum[128 + t];
        __syncthreads();
    }
    if (t < 128) l_s[t] = 1.f / l_s[t];
    __syncthreads();

    // ---------------- pass 2: O = (exp(S)/l + bias) @ V ----------------
    float oacc[2][4][4];
#pragma unroll
    for (int mi = 0; mi < 2; mi++)
#pragma unroll
        for (int ni = 0; ni < 4; ni++)
#pragma unroll
            for (int e = 0; e < 4; e++) oacc[mi][ni][e] = 0.f;

    for (int kk = 0; kk < 8; kk++) {
#pragma unroll
        for (int i = 0; i < 4; i++) {
            int f = t + i * 256;
            int r = f >> 4, cc = (f & 15) * 4;
            *(float4*)(Ks + r*68 + cc) = tf4(*(const float4*)(kg + (size_t)(kk*64 + r)*Dh + cc));
            *(float4*)(Vs + r*72 + cc) = tf4(*(const float4*)(vg + (size_t)(kk*64 + r)*Dh + cc));
        }
        __syncthreads();

        float acc[2][4][4];
#pragma unroll
        for (int mi = 0; mi < 2; mi++)
#pragma unroll
            for (int ni = 0; ni < 4; ni++)
#pragma unroll
                for (int e = 0; e < 4; e++) acc[mi][ni][e] = 0.f;

#pragma unroll
        for (int ks = 0; ks < 64; ks += 8) {
            unsigned a[2][4], b[4][2];
#pragma unroll
            for (int mi = 0; mi < 2; mi++) {
                const float* ap = Qs + (wr*32 + mi*16 + g)*68 + ks + c4;
                a[mi][0] = __float_as_uint(ap[0]);
                a[mi][1] = __float_as_uint(ap[8*68]);
                a[mi][2] = __float_as_uint(ap[4]);
                a[mi][3] = __float_as_uint(ap[8*68 + 4]);
            }
#pragma unroll
            for (int ni = 0; ni < 4; ni++) {
                const float* bp = Ks + (wc*32 + ni*8 + g)*68 + ks + c4;
                b[ni][0] = __float_as_uint(bp[0]);
                b[ni][1] = __float_as_uint(bp[4]);
            }
#pragma unroll
            for (int mi = 0; mi < 2; mi++)
#pragma unroll
                for (int ni = 0; ni < 4; ni++)
                    mma8(acc[mi][ni], a[mi], b[ni]);
        }

        // P' = exp(s)*1/l + bias[k - q + 511]
#pragma unroll
        for (int mi = 0; mi < 2; mi++) {
            int r0 = wr*32 + mi*16 + g;
            float rl0 = l_s[r0], rl1 = l_s[r0 + 8];
#pragma unroll
            for (int ni = 0; ni < 4; ni++) {
                int col = wc*32 + ni*8 + 2*c4;
                int idx0 = kk*64 + col - (q0 + r0) + (Lsz - 1);
                float p00 = __expf(acc[mi][ni][0]*scale)*rl0 + bias_s[idx0];
                float p01 = __expf(acc[mi][ni][1]*scale)*rl0 + bias_s[idx0 + 1];
                float p10 = __expf(acc[mi][ni][2]*scale)*rl1 + bias_s[idx0 - 8];
                float p11 = __expf(acc[mi][ni][3]*scale)*rl1 + bias_s[idx0 - 7];
                Ps[r0*68 + col]         = f2tf(p00);
                Ps[r0*68 + col + 1]     = f2tf(p01);
                Ps[(r0+8)*68 + col]     = f2tf(p10);
                Ps[(r0+8)*68 + col + 1] = f2tf(p11);
            }
        }
        __syncthreads();

        // O += P' @ V   (A = Ps row-major [q][k]; B frag read from row-major Vs[k][d])
#pragma unroll
        for (int ks = 0; ks < 64; ks += 8) {
            unsigned a[2][4], b[4][2];
#pragma unroll
            for (int mi = 0; mi < 2; mi++) {
                const float* ap = Ps + (wr*32 + mi*16 + g)*68 + ks + c4;
                a[mi][0] = __float_as_uint(ap[0]);
                a[mi][1] = __float_as_uint(ap[8*68]);
                a[mi][2] = __float_as_uint(ap[4]);
                a[mi][3] = __float_as_uint(ap[8*68 + 4]);
            }
#pragma unroll
            for (int ni = 0; ni < 4; ni++) {
                const float* bp = Vs + (ks + c4)*72 + wc*32 + ni*8 + g;
                b[ni][0] = __float_as_uint(bp[0]);
                b[ni][1] = __float_as_uint(bp[4*72]);
            }
#pragma unroll
            for (int mi = 0; mi < 2; mi++)
#pragma unroll
                for (int ni = 0; ni < 4; ni++)
                    mma8(oacc[mi][ni], a[mi], b[ni]);
        }
        __syncthreads();
    }

    // epilogue -> g_o in (B, L, C) layout, channel = h*64 + d
    const int bb = bh >> 3;
#pragma unroll
    for (int mi = 0; mi < 2; mi++) {
        int r0 = q0 + wr*32 + mi*16 + g;
#pragma unroll
        for (int ni = 0; ni < 4; ni++) {
            int col = wc*32 + ni*8 + 2*c4;
            float* p = g_o + ((size_t)(bb*Lsz + r0) * Csz + h*Dh + col);
            p[0] = oacc[mi][ni][0]; p[1] = oacc[mi][ni][1];
            p[8*Csz] = oacc[mi][ni][2]; p[8*Csz + 1] = oacc[mi][ni][3];
        }
    }
}

// ---------------------------------------------------------------------------
// Kernel 3: LayerNorm over C=512.  One warp per row.
// ---------------------------------------------------------------------------
__global__ void __launch_bounds__(256) ln_kernel(
    const float* __restrict__ gamma,
    const float* __restrict__ beta,
    float* __restrict__ out)
{
    const int row = blockIdx.x * 8 + (threadIdx.x >> 5);
    const int lane = threadIdx.x & 31;
    const float* xr = g_o + (size_t)row * Csz;

    float4 v[4];
    float s = 0.f;
#pragma unroll
    for (int w = 0; w < 4; w++) {
        v[w] = *(const float4*)(xr + w*128 + lane*4);
        s += (v[w].x + v[w].y) + (v[w].z + v[w].w);
    }
#pragma unroll
    for (int o = 16; o > 0; o >>= 1) s += __shfl_xor_sync(0xffffffffu, s, o);
    const float mu = s * (1.0f / Csz);

    float ss = 0.f;
#pragma unroll
    for (int w = 0; w < 4; w++) {
        float dx = v[w].x - mu, dy = v[w].y - mu, dz = v[w].z - mu, dw = v[w].w - mu;
        ss += dx*dx + dy*dy + dz*dz + dw*dw;
    }
#pragma unroll
    for (int o = 16; o > 0; o >>= 1) ss += __shfl_xor_sync(0xffffffffu, ss, o);
    const float rstd = rsqrtf(ss * (1.0f / Csz) + 1e-5f);

    float* orow = out + (size_t)row * Csz;
#pragma unroll
    for (int w = 0; w < 4; w++) {
        int c = w*128 + lane*4;
        float4 gm = *(const float4*)(gamma + c);
        float4 bt = *(const float4*)(beta + c);
        float4 r;
        r.x = gm.x * (v[w].x - mu) * rstd + bt.x;
        r.y = gm.y * (v[w].y - mu) * rstd + bt.y;
        r.z = gm.z * (v[w].z - mu) * rstd + bt.z;
        r.w = gm.w * (v[w].w - mu) * rstd + bt.w;
        *(float4*)(orow + c) = r;
    }
}

// ---------------------------------------------------------------------------
extern "C" void kernel_launch(void* const* d_in, const int* in_sizes, int n_in,
                              void* d_out, int out_size)
{
    (void)in_sizes; (void)n_in; (void)out_size;
    const float* x     = (const float*)d_in[0];
    const float* wq    = (const float*)d_in[1];
    const float* wk    = (const float*)d_in[2];
    const float* wv    = (const float*)d_in[3];
    const float* btab  = (const float*)d_in[4];
    const float* gamma = (const float*)d_in[5];
    const float* beta  = (const float*)d_in[6];
    // d_in[7] (rel_index) is analytic: k - q + L - 1; not needed.

    cudaFuncSetAttribute(attn_kernel, cudaFuncAttributeMaxDynamicSharedMemorySize, 111104);

    qkv_kernel<<<dim3(128, 24), 256>>>(x, wq, wk, wv);
    attn_kernel<<<dim3(4, 256), 256, 111104>>>(btab);
    ln_kernel<<<Msz / 8, 256>>>(gamma, beta, (float*)d_out);
}

// round 2
// speedup vs baseline: 1.0831x; 1.0831x over previous
#include <cuda_runtime.h>
#include <cstdint>

#define Bsz 32
#define Lsz 512
#define Csz 512
#define Hsz 8
#define Dh  64
#define Msz (Bsz*Lsz)   // 16384

// Scratch (device globals: allocation-free contract)
__device__ __align__(16) float g_q[Bsz*Hsz*Lsz*Dh];
__device__ __align__(16) float g_k[Bsz*Hsz*Lsz*Dh];
__device__ __align__(16) float g_v[Bsz*Hsz*Lsz*Dh];
__device__ __align__(16) float g_o[Msz*Csz];
__device__ __align__(16) float g_xt[Msz*Csz];      // tf32-rounded x
__device__ __align__(16) float g_wt[3*Csz*Csz];    // tf32-rounded wq|wk|wv

__device__ __forceinline__ float f2tf(float f){
    unsigned u; asm("cvt.rna.tf32.f32 %0, %1;" : "=r"(u) : "f"(f));
    return __uint_as_float(u);
}
__device__ __forceinline__ float4 tf4(float4 v){
    v.x = f2tf(v.x); v.y = f2tf(v.y); v.z = f2tf(v.z); v.w = f2tf(v.w);
    return v;
}
__device__ __forceinline__ void mma8(float* c, const unsigned* a, const unsigned* b){
    asm volatile("mma.sync.aligned.m16n8k8.row.col.f32.tf32.tf32.f32 "
        "{%0,%1,%2,%3}, {%4,%5,%6,%7}, {%8,%9}, {%0,%1,%2,%3};"
        : "+f"(c[0]), "+f"(c[1]), "+f"(c[2]), "+f"(c[3])
        : "r"(a[0]), "r"(a[1]), "r"(a[2]), "r"(a[3]), "r"(b[0]), "r"(b[1]));
}
__device__ __forceinline__ void ldsm4(unsigned* r, unsigned addr){
    asm volatile("ldmatrix.sync.aligned.m8n8.x4.shared.b16 {%0,%1,%2,%3}, [%4];"
        : "=r"(r[0]), "=r"(r[1]), "=r"(r[2]), "=r"(r[3]) : "r"(addr));
}
__device__ __forceinline__ void cp16(unsigned d, const void* s){
    asm volatile("cp.async.cg.shared.global [%0], [%1], 16;" :: "r"(d), "l"(s));
}
__device__ __forceinline__ void cp_commit(){ asm volatile("cp.async.commit_group;"); }
template<int N> __device__ __forceinline__ void cp_wait(){
    asm volatile("cp.async.wait_group %0;" :: "n"(N));
}

// ---------------------------------------------------------------------------
// Kernel 0: pre-round x and weights to tf32 (removes cvt from hot loops)
// ---------------------------------------------------------------------------
__global__ void __launch_bounds__(256) round_kernel(
    const float* __restrict__ x,
    const float* __restrict__ wq,
    const float* __restrict__ wk,
    const float* __restrict__ wv)
{
    const int id = blockIdx.x * 256 + threadIdx.x;   // float4 index
    const int NX = (Msz*Csz)/4;                      // 2097152
    if (id < NX) {
        ((float4*)g_xt)[id] = tf4(((const float4*)x)[id]);
    } else {
        int j = id - NX;                             // 0..196607
        int which = j >> 16, rem = j & 65535;
        const float* src = (which == 0) ? wq : (which == 1) ? wk : wv;
        ((float4*)g_wt)[(size_t)which*65536 + rem] = tf4(((const float4*)src)[rem]);
    }
}

// ---------------------------------------------------------------------------
// Kernel 1: QKV projection.  y = x @ W^T.  CTA tile 128x64, BK=32, 3-stage
// cp.async pipeline, ldmatrix fragments.  Output pre-rounded to tf32.
// ---------------------------------------------------------------------------
#define QKV_SMEM ((3*128*36 + 3*64*36)*4)

__global__ void __launch_bounds__(256) qkv_kernel()
{
    extern __shared__ float sm[];
    // As: 3 stages [128][36], Bs: 3 stages [64][36]
    const int mt = blockIdx.x;           // 0..127
    const int nt = blockIdx.y;           // 0..23
    const int which = nt >> 3;
    const int n0 = (nt & 7) * 64;
    const int m0 = mt * 128;
    const float* wgm = g_wt + (size_t)which * (Csz*Csz);
    float* dst = (which == 0) ? g_q : (which == 1) ? g_k : g_v;

    const int t = threadIdx.x;
    const int lane = t & 31, warp = t >> 5;
    const int wr = warp >> 1, wc = warp & 1;
    const int quad = lane >> 3, lr = lane & 7;
    const int g = lane >> 2, c4 = lane & 3;

    const unsigned smem_u = (unsigned)__cvta_generic_to_shared(sm);
    const unsigned B_OFF = 3*128*36*4;

    // copy indices
    int arow[4], acol[4], brow[2], bcol[2];
#pragma unroll
    for (int i = 0; i < 4; i++) { int f = t + i*256; arow[i] = f >> 3; acol[i] = (f & 7)*4; }
#pragma unroll
    for (int i = 0; i < 2; i++) { int f = t + i*256; brow[i] = f >> 3; bcol[i] = (f & 7)*4; }

    auto prefetch = [&](int it){
        int k0 = it * 32, s = it % 3;
        unsigned ab = smem_u + s*128*36*4;
        unsigned bb = smem_u + B_OFF + s*64*36*4;
#pragma unroll
        for (int i = 0; i < 4; i++)
            cp16(ab + (arow[i]*36 + acol[i])*4, g_xt + (size_t)(m0 + arow[i])*Csz + k0 + acol[i]);
#pragma unroll
        for (int i = 0; i < 2; i++)
            cp16(bb + (brow[i]*36 + bcol[i])*4, wgm + (size_t)(n0 + brow[i])*Csz + k0 + bcol[i]);
    };

    // fragment smem offsets (element units)
    int aoff[2], boff[2];
#pragma unroll
    for (int mi = 0; mi < 2; mi++)
        aoff[mi] = (wr*32 + mi*16 + (quad&1)*8 + lr)*36 + (quad>>1)*4;
#pragma unroll
    for (int li = 0; li < 2; li++)
        boff[li] = (wc*32 + li*16 + (quad>>1)*8 + lr)*36 + (quad&1)*4;

    float acc[2][4][4];
#pragma unroll
    for (int mi = 0; mi < 2; mi++)
#pragma unroll
        for (int ni = 0; ni < 4; ni++)
#pragma unroll
            for (int e = 0; e < 4; e++) acc[mi][ni][e] = 0.f;

    prefetch(0); cp_commit();
    prefetch(1); cp_commit();

    for (int it = 0; it < 16; it++) {
        cp_wait<1>();
        __syncthreads();
        if (it + 2 < 16) prefetch(it + 2);
        cp_commit();

        int s = it % 3;
        unsigned abase = smem_u + s*128*36*4;
        unsigned bbase = smem_u + B_OFF + s*64*36*4;
#pragma unroll
        for (int ks = 0; ks < 32; ks += 8) {
            unsigned a[2][4], bf[2][4];
            ldsm4(a[0],  abase + (aoff[0] + ks)*4);
            ldsm4(a[1],  abase + (aoff[1] + ks)*4);
            ldsm4(bf[0], bbase + (boff[0] + ks)*4);
            ldsm4(bf[1], bbase + (boff[1] + ks)*4);
#pragma unroll
            for (int mi = 0; mi < 2; mi++)
#pragma unroll
                for (int ni = 0; ni < 4; ni++)
                    mma8(acc[mi][ni], a[mi], &bf[ni>>1][(ni&1)*2]);
        }
    }

    // epilogue: n-tile 64-wide/aligned -> single head.  Write tf32-rounded.
    const int h = n0 >> 6;
#pragma unroll
    for (int mi = 0; mi < 2; mi++) {
        int row = m0 + wr*32 + mi*16 + g;
        int bb2 = row >> 9, ll = row & 511;
#pragma unroll
        for (int ni = 0; ni < 4; ni++) {
            int col = wc*32 + ni*8 + 2*c4;
            float* p = dst + (((size_t)(bb2*Hsz + h) * Lsz + ll) * Dh + col);
            p[0]        = f2tf(acc[mi][ni][0]);
            p[1]        = f2tf(acc[mi][ni][1]);
            p[8*Dh]     = f2tf(acc[mi][ni][2]);
            p[8*Dh + 1] = f2tf(acc[mi][ni][3]);
        }
    }
}

// ---------------------------------------------------------------------------
// Kernel 2: fused attention per (b,h,q-tile of 128).
// Pass 1: l[q] = sum_k exp(s) (register-accumulated).
// Pass 2: P' = exp(s)/l + bias; O = P' @ V.  3-stage cp.async for K/V tiles.
// ---------------------------------------------------------------------------
// smem float offsets
#define AQ_OFF   0                    // Qs [128][68]
#define AP_OFF   8704                 // Ps [128][68]
#define AK_OFF   17408                // Ks 3x [64][68]
#define AV_OFF   (17408 + 3*4352)     // Vs 3x [64][72]
#define AB_OFF   (AV_OFF + 3*4608)    // bias [1024]
#define AL_OFF   (AB_OFF + 1024)      // l_s [128]
#define AS_OFF   (AL_OFF + 128)       // lsum [256]
#define ATTN_SMEM ((AS_OFF + 256)*4)

__global__ void __launch_bounds__(256) attn_kernel(const float* __restrict__ bias_table)
{
    extern __shared__ float sm[];
    float* bias_s = sm + AB_OFF;
    float* l_s    = sm + AL_OFF;
    float* lsum   = sm + AS_OFF;
    float* Ps     = sm + AP_OFF;

    const int qt = blockIdx.x;          // 0..3
    const int bh = blockIdx.y;          // 0..255
    const int h = bh & (Hsz - 1);
    const int q0 = qt * 128;
    const int t = threadIdx.x;
    const int lane = t & 31, warp = t >> 5;
    const int wr = warp >> 1, wc = warp & 1;
    const int quad = lane >> 3, lr = lane & 7;
    const int g = lane >> 2, c4 = lane & 3;

    const float* qg = g_q + (size_t)bh * Lsz * Dh;
    const float* kg = g_k + (size_t)bh * Lsz * Dh;
    const float* vg = g_v + (size_t)bh * Lsz * Dh;
    const float scale = 0.04419417382415922f;   // 512^-0.5

    const unsigned smem_u = (unsigned)__cvta_generic_to_shared(sm);

    int crow[4], ccol[4];
#pragma unroll
    for (int i = 0; i < 4; i++) { int f = t + i*256; crow[i] = f >> 4; ccol[i] = (f & 15)*4; }

    auto cpK = [&](int it){
        int s = it % 3;
        unsigned kb = smem_u + (AK_OFF + s*4352)*4;
#pragma unroll
        for (int i = 0; i < 4; i++)
            cp16(kb + (crow[i]*68 + ccol[i])*4, kg + (size_t)(it*64 + crow[i])*Dh + ccol[i]);
    };
    auto cpV = [&](int it){
        int s = it % 3;
        unsigned vb = smem_u + (AV_OFF + s*4608)*4;
#pragma unroll
        for (int i = 0; i < 4; i++)
            cp16(vb + (crow[i]*72 + ccol[i])*4, vg + (size_t)(it*64 + crow[i])*Dh + ccol[i]);
    };

    // Q tile load (group 0)
    {
        unsigned qb = smem_u + AQ_OFF*4;
#pragma unroll
        for (int i = 0; i < 8; i++) {
            int f = t + i*256, r = f >> 4, cc = (f & 15)*4;
            cp16(qb + (r*68 + cc)*4, qg + (size_t)(q0 + r)*Dh + cc);
        }
        cp_commit();
    }
    cpK(0); cp_commit();
    cpK(1); cp_commit();

    // bias (normal loads; used only in pass 2)
    for (int i = t; i < 2*Lsz - 1; i += 256) bias_s[i] = bias_table[(size_t)i*Hsz + h];

    // fragment offsets (stride 68: Qs, Ks, Ps)
    int aoff[2], boff[2];
#pragma unroll
    for (int mi = 0; mi < 2; mi++)
        aoff[mi] = (wr*32 + mi*16 + (quad&1)*8 + lr)*68 + (quad>>1)*4;
#pragma unroll
    for (int li = 0; li < 2; li++)
        boff[li] = (wc*32 + li*16 + (quad>>1)*8 + lr)*68 + (quad&1)*4;

    const unsigned qbase = smem_u + AQ_OFF*4;
    const unsigned pbase = smem_u + AP_OFF*4;

    // ---------------- pass 1: row sums (register accumulation) -------------
    float s0[2] = {0.f, 0.f}, s1[2] = {0.f, 0.f};

    for (int kk = 0; kk < 8; kk++) {
        cp_wait<1>();
        __syncthreads();
        if (kk + 2 < 8) cpK(kk + 2);
        cp_commit();

        unsigned kbase = smem_u + (AK_OFF + (kk%3)*4352)*4;

        float acc[2][4][4];
#pragma unroll
        for (int mi = 0; mi < 2; mi++)
#pragma unroll
            for (int ni = 0; ni < 4; ni++)
#pragma unroll
                for (int e = 0; e < 4; e++) acc[mi][ni][e] = 0.f;

#pragma unroll
        for (int ks = 0; ks < 64; ks += 8) {
            unsigned a[2][4], bf[2][4];
            ldsm4(a[0],  qbase + (aoff[0] + ks)*4);
            ldsm4(a[1],  qbase + (aoff[1] + ks)*4);
            ldsm4(bf[0], kbase + (boff[0] + ks)*4);
            ldsm4(bf[1], kbase + (boff[1] + ks)*4);
#pragma unroll
            for (int mi = 0; mi < 2; mi++)
#pragma unroll
                for (int ni = 0; ni < 4; ni++)
                    mma8(acc[mi][ni], a[mi], &bf[ni>>1][(ni&1)*2]);
        }

#pragma unroll
        for (int mi = 0; mi < 2; mi++) {
            float t0 = 0.f, t1 = 0.f;
#pragma unroll
            for (int ni = 0; ni < 4; ni++) {
                t0 += __expf(acc[mi][ni][0]*scale) + __expf(acc[mi][ni][1]*scale);
                t1 += __expf(acc[mi][ni][2]*scale) + __expf(acc[mi][ni][3]*scale);
            }
            s0[mi] += t0; s1[mi] += t1;
        }
    }

#pragma unroll
    for (int mi = 0; mi < 2; mi++) {
        float a0 = s0[mi], a1 = s1[mi];
        a0 += __shfl_xor_sync(0xffffffffu, a0, 1);
        a0 += __shfl_xor_sync(0xffffffffu, a0, 2);
        a1 += __shfl_xor_sync(0xffffffffu, a1, 1);
        a1 += __shfl_xor_sync(0xffffffffu, a1, 2);
        if (c4 == 0) {
            lsum[wc*128 + wr*32 + mi*16 + g]     = a0;
            lsum[wc*128 + wr*32 + mi*16 + g + 8] = a1;
        }
    }
    __syncthreads();
    if (t < 128) l_s[t] = 1.f / (lsum[t] + lsum[128 + t]);
    __syncthreads();

    // ---------------- pass 2: O = (exp(S)/l + bias) @ V --------------------
    cpK(0); cpV(0); cp_commit();
    cpK(1); cpV(1); cp_commit();

    float oacc[2][4][4];
#pragma unroll
    for (int mi = 0; mi < 2; mi++)
#pragma unroll
        for (int ni = 0; ni < 4; ni++)
#pragma unroll
            for (int e = 0; e < 4; e++) oacc[mi][ni][e] = 0.f;

    for (int kk = 0; kk < 8; kk++) {
        cp_wait<1>();
        __syncthreads();          // KV stage ready; prev Ps fully consumed
        if (kk + 2 < 8) { cpK(kk + 2); cpV(kk + 2); }
        cp_commit();

        unsigned kbase = smem_u + (AK_OFF + (kk%3)*4352)*4;
        float* Vst = sm + AV_OFF + (kk%3)*4608;

        float acc[2][4][4];
#pragma unroll
        for (int mi = 0; mi < 2; mi++)
#pragma unroll
            for (int ni = 0; ni < 4; ni++)
#pragma unroll
                for (int e = 0; e < 4; e++) acc[mi][ni][e] = 0.f;

#pragma unroll
        for (int ks = 0; ks < 64; ks += 8) {
            unsigned a[2][4], bf[2][4];
            ldsm4(a[0],  qbase + (aoff[0] + ks)*4);
            ldsm4(a[1],  qbase + (aoff[1] + ks)*4);
            ldsm4(bf[0], kbase + (boff[0] + ks)*4);
            ldsm4(bf[1], kbase + (boff[1] + ks)*4);
#pragma unroll
            for (int mi = 0; mi < 2; mi++)
#pragma unroll
                for (int ni = 0; ni < 4; ni++)
                    mma8(acc[mi][ni], a[mi], &bf[ni>>1][(ni&1)*2]);
        }

        // P' = exp(s)/l + bias[k - q + 511], rounded to tf32
#pragma unroll
        for (int mi = 0; mi < 2; mi++) {
            int r0 = wr*32 + mi*16 + g;
            float rl0 = l_s[r0], rl1 = l_s[r0 + 8];
#pragma unroll
            for (int ni = 0; ni < 4; ni++) {
                int col = wc*32 + ni*8 + 2*c4;
                int idx0 = kk*64 + col - (q0 + r0) + (Lsz - 1);
                float p00 = __expf(acc[mi][ni][0]*scale)*rl0 + bias_s[idx0];
                float p01 = __expf(acc[mi][ni][1]*scale)*rl0 + bias_s[idx0 + 1];
                float p10 = __expf(acc[mi][ni][2]*scale)*rl1 + bias_s[idx0 - 8];
                float p11 = __expf(acc[mi][ni][3]*scale)*rl1 + bias_s[idx0 - 7];
                Ps[r0*68 + col]         = f2tf(p00);
                Ps[r0*68 + col + 1]     = f2tf(p01);
                Ps[(r0+8)*68 + col]     = f2tf(p10);
                Ps[(r0+8)*68 + col + 1] = f2tf(p11);
            }
        }
        __syncthreads();

        // O += P' @ V
#pragma unroll
        for (int ks = 0; ks < 64; ks += 8) {
            unsigned a[2][4], b[4][2];
            ldsm4(a[0], pbase + (aoff[0] + ks)*4);
            ldsm4(a[1], pbase + (aoff[1] + ks)*4);
#pragma unroll
            for (int ni = 0; ni < 4; ni++) {
                const float* bp = Vst + (ks + c4)*72 + wc*32 + ni*8 + g;
                b[ni][0] = __float_as_uint(bp[0]);
                b[ni][1] = __float_as_uint(bp[4*72]);
            }
#pragma unroll
            for (int mi = 0; mi < 2; mi++)
#pragma unroll
                for (int ni = 0; ni < 4; ni++)
                    mma8(oacc[mi][ni], a[mi], b[ni]);
        }
    }

    // epilogue -> g_o in (B, L, C) layout, channel = h*64 + d
    const int bb = bh >> 3;
#pragma unroll
    for (int mi = 0; mi < 2; mi++) {
        int r0 = q0 + wr*32 + mi*16 + g;
#pragma unroll
        for (int ni = 0; ni < 4; ni++) {
            int col = wc*32 + ni*8 + 2*c4;
            float* p = g_o + ((size_t)(bb*Lsz + r0) * Csz + h*Dh + col);
            p[0] = oacc[mi][ni][0]; p[1] = oacc[mi][ni][1];
            p[8*Csz] = oacc[mi][ni][2]; p[8*Csz + 1] = oacc[mi][ni][3];
        }
    }
}

// ---------------------------------------------------------------------------
// Kernel 3: LayerNorm over C=512.  One warp per row.
// ---------------------------------------------------------------------------
__global__ void __launch_bounds__(256) ln_kernel(
    const float* __restrict__ gamma,
    const float* __restrict__ beta,
    float* __restrict__ out)
{
    const int row = blockIdx.x * 8 + (threadIdx.x >> 5);
    const int lane = threadIdx.x & 31;
    const float* xr = g_o + (size_t)row * Csz;

    float4 v[4];
    float s = 0.f;
#pragma unroll
    for (int w = 0; w < 4; w++) {
        v[w] = *(const float4*)(xr + w*128 + lane*4);
        s += (v[w].x + v[w].y) + (v[w].z + v[w].w);
    }
#pragma unroll
    for (int o = 16; o > 0; o >>= 1) s += __shfl_xor_sync(0xffffffffu, s, o);
    const float mu = s * (1.0f / Csz);

    float ss = 0.f;
#pragma unroll
    for (int w = 0; w < 4; w++) {
        float dx = v[w].x - mu, dy = v[w].y - mu, dz = v[w].z - mu, dw = v[w].w - mu;
        ss += dx*dx + dy*dy + dz*dz + dw*dw;
    }
#pragma unroll
    for (int o = 16; o > 0; o >>= 1) ss += __shfl_xor_sync(0xffffffffu, ss, o);
    const float rstd = rsqrtf(ss * (1.0f / Csz) + 1e-5f);

    float* orow = out + (size_t)row * Csz;
#pragma unroll
    for (int w = 0; w < 4; w++) {
        int c = w*128 + lane*4;
        float4 gm = *(const float4*)(gamma + c);
        float4 bt = *(const float4*)(beta + c);
        float4 r;
        r.x = gm.x * (v[w].x - mu) * rstd + bt.x;
        r.y = gm.y * (v[w].y - mu) * rstd + bt.y;
        r.z = gm.z * (v[w].z - mu) * rstd + bt.z;
        r.w = gm.w * (v[w].w - mu) * rstd + bt.w;
        *(float4*)(orow + c) = r;
    }
}

// ---------------------------------------------------------------------------
extern "C" void kernel_launch(void* const* d_in, const int* in_sizes, int n_in,
                              void* d_out, int out_size)
{
    (void)in_sizes; (void)n_in; (void)out_size;
    const float* x     = (const float*)d_in[0];
    const float* wq    = (const float*)d_in[1];
    const float* wk    = (const float*)d_in[2];
    const float* wv    = (const float*)d_in[3];
    const float* btab  = (const float*)d_in[4];
    const float* gamma = (const float*)d_in[5];
    const float* beta  = (const float*)d_in[6];
    // d_in[7] (rel_index) is analytic: k - q + L - 1; not needed.

    cudaFuncSetAttribute(qkv_kernel,  cudaFuncAttributeMaxDynamicSharedMemorySize, QKV_SMEM);
    cudaFuncSetAttribute(attn_kernel, cudaFuncAttributeMaxDynamicSharedMemorySize, ATTN_SMEM);

    round_kernel<<<(2097152 + 196608) / 256, 256>>>(x, wq, wk, wv);
    qkv_kernel<<<dim3(128, 24), 256, QKV_SMEM>>>();
    attn_kernel<<<dim3(4, 256), 256, ATTN_SMEM>>>(btab);
    ln_kernel<<<Msz / 8, 256>>>(gamma, beta, (float*)d_out);
}

// round 4
// speedup vs baseline: 1.1611x; 1.0720x over previous
#include <cuda_runtime.h>
#include <cstdint>

#define Bsz 32
#define Lsz 512
#define Csz 512
#define Hsz 8
#define Dh  64
#define Msz (Bsz*Lsz)   // 16384

// Scratch (device globals: allocation-free contract)
__device__ __align__(16) float g_q[Bsz*Hsz*Lsz*Dh];
__device__ __align__(16) float g_k[Bsz*Hsz*Lsz*Dh];
__device__ __align__(16) float g_v[Bsz*Hsz*Lsz*Dh];
__device__ __align__(16) float g_o[Msz*Csz];
__device__ __align__(16) float g_xt[Msz*Csz];      // tf32-rounded x
__device__ __align__(16) float g_wt[3*Csz*Csz];    // tf32-rounded wq|wk|wv

__device__ __forceinline__ float f2tf(float f){
    unsigned u; asm("cvt.rna.tf32.f32 %0, %1;" : "=r"(u) : "f"(f));
    return __uint_as_float(u);
}
__device__ __forceinline__ float4 tf4(float4 v){
    v.x = f2tf(v.x); v.y = f2tf(v.y); v.z = f2tf(v.z); v.w = f2tf(v.w);
    return v;
}
__device__ __forceinline__ void mma8(float* c, const unsigned* a, const unsigned* b){
    asm volatile("mma.sync.aligned.m16n8k8.row.col.f32.tf32.tf32.f32 "
        "{%0,%1,%2,%3}, {%4,%5,%6,%7}, {%8,%9}, {%0,%1,%2,%3};"
        : "+f"(c[0]), "+f"(c[1]), "+f"(c[2]), "+f"(c[3])
        : "r"(a[0]), "r"(a[1]), "r"(a[2]), "r"(a[3]), "r"(b[0]), "r"(b[1]));
}
__device__ __forceinline__ void ldsm4(unsigned* r, unsigned addr){
    asm volatile("ldmatrix.sync.aligned.m8n8.x4.shared.b16 {%0,%1,%2,%3}, [%4];"
        : "=r"(r[0]), "=r"(r[1]), "=r"(r[2]), "=r"(r[3]) : "r"(addr));
}
__device__ __forceinline__ void cp16(unsigned d, const void* s){
    asm volatile("cp.async.cg.shared.global [%0], [%1], 16;" :: "r"(d), "l"(s));
}
__device__ __forceinline__ void cp_commit(){ asm volatile("cp.async.commit_group;"); }
template<int N> __device__ __forceinline__ void cp_wait(){
    asm volatile("cp.async.wait_group %0;" :: "n"(N));
}

// ---------------------------------------------------------------------------
// Kernel 0: pre-round x and weights to tf32 (removes cvt from hot loops)
// ---------------------------------------------------------------------------
__global__ void __launch_bounds__(256) round_kernel(
    const float* __restrict__ x,
    const float* __restrict__ wq,
    const float* __restrict__ wk,
    const float* __restrict__ wv)
{
    const int id = blockIdx.x * 256 + threadIdx.x;   // float4 index
    const int NX = (Msz*Csz)/4;                      // 2097152
    if (id < NX) {
        ((float4*)g_xt)[id] = tf4(((const float4*)x)[id]);
    } else {
        int j = id - NX;                             // 0..196607
        int which = j >> 16, rem = j & 65535;
        const float* src = (which == 0) ? wq : (which == 1) ? wk : wv;
        ((float4*)g_wt)[(size_t)which*65536 + rem] = tf4(((const float4*)src)[rem]);
    }
}

// ---------------------------------------------------------------------------
// Kernel 1: QKV projection.  y = x @ W^T.  CTA tile 128x128, BK=32, 3-stage
// cp.async pipeline, ldmatrix fragments.  Warp tile 32x64 (4x2 warp grid).
// ---------------------------------------------------------------------------
#define QKV_SMEM (3*(128*36 + 128*36)*4)   // 110592 bytes

__global__ void __launch_bounds__(256) qkv_kernel()
{
    extern __shared__ float sm[];
    const int mt = blockIdx.x;           // 0..127
    const int nt = blockIdx.y;           // 0..11
    const int which = nt >> 2;
    const int n0 = (nt & 3) * 128;
    const int m0 = mt * 128;
    const float* wgm = g_wt + (size_t)which * (Csz*Csz);
    float* dst = (which == 0) ? g_q : (which == 1) ? g_k : g_v;

    const int t = threadIdx.x;
    const int lane = t & 31, warp = t >> 5;
    const int wr = warp >> 1, wc = warp & 1;
    const int quad = lane >> 3, lr = lane & 7;
    const int g = lane >> 2, c4 = lane & 3;

    const unsigned smem_u = (unsigned)__cvta_generic_to_shared(sm);
    const unsigned B_OFF = 3*128*36*4;

    // copy indices: 128 rows x 8 float4 per tile -> 4 cp16 per thread each
    int arow[4], acol[4];
#pragma unroll
    for (int i = 0; i < 4; i++) { int f = t + i*256; arow[i] = f >> 3; acol[i] = (f & 7)*4; }

    auto prefetch = [&](int it){
        int k0 = it * 32, s = it % 3;
        unsigned ab = smem_u + s*128*36*4;
        unsigned bb = smem_u + B_OFF + s*128*36*4;
#pragma unroll
        for (int i = 0; i < 4; i++) {
            cp16(ab + (arow[i]*36 + acol[i])*4, g_xt + (size_t)(m0 + arow[i])*Csz + k0 + acol[i]);
            cp16(bb + (arow[i]*36 + acol[i])*4, wgm  + (size_t)(n0 + arow[i])*Csz + k0 + acol[i]);
        }
    };

    // fragment smem offsets (element units, stride 36)
    int aoff[2], boff[4];
#pragma unroll
    for (int mi = 0; mi < 2; mi++)
        aoff[mi] = (wr*32 + mi*16 + (quad&1)*8 + lr)*36 + (quad>>1)*4;
#pragma unroll
    for (int li = 0; li < 4; li++)
        boff[li] = (wc*64 + li*16 + (quad>>1)*8 + lr)*36 + (quad&1)*4;

    float acc[2][8][4];
#pragma unroll
    for (int mi = 0; mi < 2; mi++)
#pragma unroll
        for (int ni = 0; ni < 8; ni++)
#pragma unroll
            for (int e = 0; e < 4; e++) acc[mi][ni][e] = 0.f;

    prefetch(0); cp_commit();
    prefetch(1); cp_commit();

    for (int it = 0; it < 16; it++) {
        cp_wait<1>();
        __syncthreads();
        if (it + 2 < 16) prefetch(it + 2);
        cp_commit();

        int s = it % 3;
        unsigned abase = smem_u + s*128*36*4;
        unsigned bbase = smem_u + B_OFF + s*128*36*4;
#pragma unroll
        for (int ks = 0; ks < 32; ks += 8) {
            unsigned a[2][4], bf[4][4];
            ldsm4(a[0],  abase + (aoff[0] + ks)*4);
            ldsm4(a[1],  abase + (aoff[1] + ks)*4);
#pragma unroll
            for (int li = 0; li < 4; li++)
                ldsm4(bf[li], bbase + (boff[li] + ks)*4);
#pragma unroll
            for (int mi = 0; mi < 2; mi++)
#pragma unroll
                for (int ni = 0; ni < 8; ni++)
                    mma8(acc[mi][ni], a[mi], &bf[ni>>1][(ni&1)*2]);
        }
    }

    // epilogue: wc half selects head parity; write tf32-rounded q/k/v
#pragma unroll
    for (int mi = 0; mi < 2; mi++) {
        int row = m0 + wr*32 + mi*16 + g;
        int bb2 = row >> 9, ll = row & 511;
        int h = (n0 >> 6) + wc;
        float* base = dst + (((size_t)(bb2*Hsz + h) * Lsz + ll) * Dh);
#pragma unroll
        for (int ni = 0; ni < 8; ni++) {
            int col = ni*8 + 2*c4;    // d within head (0..62)
            float* p = base + col;
            p[0]        = f2tf(acc[mi][ni][0]);
            p[1]        = f2tf(acc[mi][ni][1]);
            p[8*Dh]     = f2tf(acc[mi][ni][2]);
            p[8*Dh + 1] = f2tf(acc[mi][ni][3]);
        }
    }
}

// ---------------------------------------------------------------------------
// Kernel 2: fused attention per (b,h,q-tile of 128).
// Pass 1: l[q] = sum_k exp(s) (register-accumulated).
// Pass 2: P' = exp(s)/l + bias; O = P' @ V.  3-stage cp.async for K/V tiles.
// ---------------------------------------------------------------------------
#define AQ_OFF   0                    // Qs [128][68]
#define AP_OFF   8704                 // Ps [128][68]
#define AK_OFF   17408                // Ks 3x [64][68]
#define AV_OFF   (17408 + 3*4352)     // Vs 3x [64][72]
#define AB_OFF   (AV_OFF + 3*4608)    // bias [1024]
#define AL_OFF   (AB_OFF + 1024)      // l_s [128]
#define AS_OFF   (AL_OFF + 128)       // lsum [256]
#define ATTN_SMEM ((AS_OFF + 256)*4)

__global__ void __launch_bounds__(256) attn_kernel(const float* __restrict__ bias_table)
{
    extern __shared__ float sm[];
    float* bias_s = sm + AB_OFF;
    float* l_s    = sm + AL_OFF;
    float* lsum   = sm + AS_OFF;
    float* Ps     = sm + AP_OFF;

    const int qt = blockIdx.x;          // 0..3
    const int bh = blockIdx.y;          // 0..255
    const int h = bh & (Hsz - 1);
    const int q0 = qt * 128;
    const int t = threadIdx.x;
    const int lane = t & 31, warp = t >> 5;
    const int wr = warp >> 1, wc = warp & 1;
    const int quad = lane >> 3, lr = lane & 7;
    const int g = lane >> 2, c4 = lane & 3;

    const float* qg = g_q + (size_t)bh * Lsz * Dh;
    const float* kg = g_k + (size_t)bh * Lsz * Dh;
    const float* vg = g_v + (size_t)bh * Lsz * Dh;
    const float scale = 0.04419417382415922f;   // 512^-0.5

    const unsigned smem_u = (unsigned)__cvta_generic_to_shared(sm);

    int crow[4], ccol[4];
#pragma unroll
    for (int i = 0; i < 4; i++) { int f = t + i*256; crow[i] = f >> 4; ccol[i] = (f & 15)*4; }

    auto cpK = [&](int it){
        int s = it % 3;
        unsigned kb = smem_u + (AK_OFF + s*4352)*4;
#pragma unroll
        for (int i = 0; i < 4; i++)
            cp16(kb + (crow[i]*68 + ccol[i])*4, kg + (size_t)(it*64 + crow[i])*Dh + ccol[i]);
    };
    auto cpV = [&](int it){
        int s = it % 3;
        unsigned vb = smem_u + (AV_OFF + s*4608)*4;
#pragma unroll
        for (int i = 0; i < 4; i++)
            cp16(vb + (crow[i]*72 + ccol[i])*4, vg + (size_t)(it*64 + crow[i])*Dh + ccol[i]);
    };

    // Q tile load (group 0)
    {
        unsigned qb = smem_u + AQ_OFF*4;
#pragma unroll
        for (int i = 0; i < 8; i++) {
            int f = t + i*256, r = f >> 4, cc = (f & 15)*4;
            cp16(qb + (r*68 + cc)*4, qg + (size_t)(q0 + r)*Dh + cc);
        }
        cp_commit();
    }
    cpK(0); cp_commit();
    cpK(1); cp_commit();

    // bias (normal loads; used only in pass 2)
    for (int i = t; i < 2*Lsz - 1; i += 256) bias_s[i] = bias_table[(size_t)i*Hsz + h];

    // fragment offsets (stride 68: Qs, Ks, Ps)
    int aoff[2], boff[2];
#pragma unroll
    for (int mi = 0; mi < 2; mi++)
        aoff[mi] = (wr*32 + mi*16 + (quad&1)*8 + lr)*68 + (quad>>1)*4;
#pragma unroll
    for (int li = 0; li < 2; li++)
        boff[li] = (wc*32 + li*16 + (quad>>1)*8 + lr)*68 + (quad&1)*4;

    const unsigned qbase = smem_u + AQ_OFF*4;
    const unsigned pbase = smem_u + AP_OFF*4;

    // ---------------- pass 1: row sums (register accumulation) -------------
    float s0[2] = {0.f, 0.f}, s1[2] = {0.f, 0.f};

    for (int kk = 0; kk < 8; kk++) {
        cp_wait<1>();
        __syncthreads();
        if (kk + 2 < 8) cpK(kk + 2);
        cp_commit();

        unsigned kbase = smem_u + (AK_OFF + (kk%3)*4352)*4;

        float acc[2][4][4];
#pragma unroll
        for (int mi = 0; mi < 2; mi++)
#pragma unroll
            for (int ni = 0; ni < 4; ni++)
#pragma unroll
                for (int e = 0; e < 4; e++) acc[mi][ni][e] = 0.f;

#pragma unroll
        for (int ks = 0; ks < 64; ks += 8) {
            unsigned a[2][4], bf[2][4];
            ldsm4(a[0],  qbase + (aoff[0] + ks)*4);
            ldsm4(a[1],  qbase + (aoff[1] + ks)*4);
            ldsm4(bf[0], kbase + (boff[0] + ks)*4);
            ldsm4(bf[1], kbase + (boff[1] + ks)*4);
#pragma unroll
            for (int mi = 0; mi < 2; mi++)
#pragma unroll
                for (int ni = 0; ni < 4; ni++)
                    mma8(acc[mi][ni], a[mi], &bf[ni>>1][(ni&1)*2]);
        }

#pragma unroll
        for (int mi = 0; mi < 2; mi++) {
            float t0 = 0.f, t1 = 0.f;
#pragma unroll
            for (int ni = 0; ni < 4; ni++) {
                t0 += __expf(acc[mi][ni][0]*scale) + __expf(acc[mi][ni][1]*scale);
                t1 += __expf(acc[mi][ni][2]*scale) + __expf(acc[mi][ni][3]*scale);
            }
            s0[mi] += t0; s1[mi] += t1;
        }
    }

#pragma unroll
    for (int mi = 0; mi < 2; mi++) {
        float a0 = s0[mi], a1 = s1[mi];
        a0 += __shfl_xor_sync(0xffffffffu, a0, 1);
        a0 += __shfl_xor_sync(0xffffffffu, a0, 2);
        a1 += __shfl_xor_sync(0xffffffffu, a1, 1);
        a1 += __shfl_xor_sync(0xffffffffu, a1, 2);
        if (c4 == 0) {
            lsum[wc*128 + wr*32 + mi*16 + g]     = a0;
            lsum[wc*128 + wr*32 + mi*16 + g + 8] = a1;
        }
    }
    __syncthreads();
    if (t < 128) l_s[t] = 1.f / (lsum[t] + lsum[128 + t]);
    __syncthreads();

    // ---------------- pass 2: O = (exp(S)/l + bias) @ V --------------------
    cpK(0); cpV(0); cp_commit();
    cpK(1); cpV(1); cp_commit();

    float oacc[2][4][4];
#pragma unroll
    for (int mi = 0; mi < 2; mi++)
#pragma unroll
        for (int ni = 0; ni < 4; ni++)
#pragma unroll
            for (int e = 0; e < 4; e++) oacc[mi][ni][e] = 0.f;

    for (int kk = 0; kk < 8; kk++) {
        cp_wait<1>();
        __syncthreads();          // KV stage ready; prev Ps fully consumed
        if (kk + 2 < 8) { cpK(kk + 2); cpV(kk + 2); }
        cp_commit();

        unsigned kbase = smem_u + (AK_OFF + (kk%3)*4352)*4;
        float* Vst = sm + AV_OFF + (kk%3)*4608;

        float acc[2][4][4];
#pragma unroll
        for (int mi = 0; mi < 2; mi++)
#pragma unroll
            for (int ni = 0; ni < 4; ni++)
#pragma unroll
                for (int e = 0; e < 4; e++) acc[mi][ni][e] = 0.f;

#pragma unroll
        for (int ks = 0; ks < 64; ks += 8) {
            unsigned a[2][4], bf[2][4];
            ldsm4(a[0],  qbase + (aoff[0] + ks)*4);
            ldsm4(a[1],  qbase + (aoff[1] + ks)*4);
            ldsm4(bf[0], kbase + (boff[0] + ks)*4);
            ldsm4(bf[1], kbase + (boff[1] + ks)*4);
#pragma unroll
            for (int mi = 0; mi < 2; mi++)
#pragma unroll
                for (int ni = 0; ni < 4; ni++)
                    mma8(acc[mi][ni], a[mi], &bf[ni>>1][(ni&1)*2]);
        }

        // P' = exp(s)/l + bias[k - q + 511], rounded to tf32
#pragma unroll
        for (int mi = 0; mi < 2; mi++) {
            int r0 = wr*32 + mi*16 + g;
            float rl0 = l_s[r0], rl1 = l_s[r0 + 8];
#pragma unroll
            for (int ni = 0; ni < 4; ni++) {
                int col = wc*32 + ni*8 + 2*c4;
                int idx0 = kk*64 + col - (q0 + r0) + (Lsz - 1);
                float p00 = __expf(acc[mi][ni][0]*scale)*rl0 + bias_s[idx0];
                float p01 = __expf(acc[mi][ni][1]*scale)*rl0 + bias_s[idx0 + 1];
                float p10 = __expf(acc[mi][ni][2]*scale)*rl1 + bias_s[idx0 - 8];
                float p11 = __expf(acc[mi][ni][3]*scale)*rl1 + bias_s[idx0 - 7];
                Ps[r0*68 + col]         = f2tf(p00);
                Ps[r0*68 + col + 1]     = f2tf(p01);
                Ps[(r0+8)*68 + col]     = f2tf(p10);
                Ps[(r0+8)*68 + col + 1] = f2tf(p11);
            }
        }
        __syncthreads();

        // O += P' @ V
#pragma unroll
        for (int ks = 0; ks < 64; ks += 8) {
            unsigned a[2][4], b[4][2];
            ldsm4(a[0], pbase + (aoff[0] + ks)*4);
            ldsm4(a[1], pbase + (aoff[1] + ks)*4);
#pragma unroll
            for (int ni = 0; ni < 4; ni++) {
                const float* bp = Vst + (ks + c4)*72 + wc*32 + ni*8 + g;
                b[ni][0] = __float_as_uint(bp[0]);
                b[ni][1] = __float_as_uint(bp[4*72]);
            }
#pragma unroll
            for (int mi = 0; mi < 2; mi++)
#pragma unroll
                for (int ni = 0; ni < 4; ni++)
                    mma8(oacc[mi][ni], a[mi], b[ni]);
        }
    }

    // epilogue -> g_o in (B, L, C) layout, channel = h*64 + d
    const int bb = bh >> 3;
#pragma unroll
    for (int mi = 0; mi < 2; mi++) {
        int r0 = q0 + wr*32 + mi*16 + g;
#pragma unroll
        for (int ni = 0; ni < 4; ni++) {
            int col = wc*32 + ni*8 + 2*c4;
            float* p = g_o + ((size_t)(bb*Lsz + r0) * Csz + h*Dh + col);
            p[0] = oacc[mi][ni][0]; p[1] = oacc[mi][ni][1];
            p[8*Csz] = oacc[mi][ni][2]; p[8*Csz + 1] = oacc[mi][ni][3];
        }
    }
}

// ---------------------------------------------------------------------------
// Kernel 3: LayerNorm over C=512.  One warp per row.
// ---------------------------------------------------------------------------
__global__ void __launch_bounds__(256) ln_kernel(
    const float* __restrict__ gamma,
    const float* __restrict__ beta,
    float* __restrict__ out)
{
    const int row = blockIdx.x * 8 + (threadIdx.x >> 5);
    const int lane = threadIdx.x & 31;
    const float* xr = g_o + (size_t)row * Csz;

    float4 v[4];
    float s = 0.f;
#pragma unroll
    for (int w = 0; w < 4; w++) {
        v[w] = *(const float4*)(xr + w*128 + lane*4);
        s += (v[w].x + v[w].y) + (v[w].z + v[w].w);
    }
#pragma unroll
    for (int o = 16; o > 0; o >>= 1) s += __shfl_xor_sync(0xffffffffu, s, o);
    const float mu = s * (1.0f / Csz);

    float ss = 0.f;
#pragma unroll
    for (int w = 0; w < 4; w++) {
        float dx = v[w].x - mu, dy = v[w].y - mu, dz = v[w].z - mu, dw = v[w].w - mu;
        ss += dx*dx + dy*dy + dz*dz + dw*dw;
    }
#pragma unroll
    for (int o = 16; o > 0; o >>= 1) ss += __shfl_xor_sync(0xffffffffu, ss, o);
    const float rstd = rsqrtf(ss * (1.0f / Csz) + 1e-5f);

    float* orow = out + (size_t)row * Csz;
#pragma unroll
    for (int w = 0; w < 4; w++) {
        int c = w*128 + lane*4;
        float4 gm = *(const float4*)(gamma + c);
        float4 bt = *(const float4*)(beta + c);
        float4 r;
        r.x = gm.x * (v[w].x - mu) * rstd + bt.x;
        r.y = gm.y * (v[w].y - mu) * rstd + bt.y;
        r.z = gm.z * (v[w].z - mu) * rstd + bt.z;
        r.w = gm.w * (v[w].w - mu) * rstd + bt.w;
        *(float4*)(orow + c) = r;
    }
}

// ---------------------------------------------------------------------------
extern "C" void kernel_launch(void* const* d_in, const int* in_sizes, int n_in,
                              void* d_out, int out_size)
{
    (void)in_sizes; (void)n_in; (void)out_size;
    const float* x     = (const float*)d_in[0];
    const float* wq    = (const float*)d_in[1];
    const float* wk    = (const float*)d_in[2];
    const float* wv    = (const float*)d_in[3];
    const float* btab  = (const float*)d_in[4];
    const float* gamma = (const float*)d_in[5];
    const float* beta  = (const float*)d_in[6];
    // d_in[7] (rel_index) is analytic: k - q + L - 1; not needed.

    cudaFuncSetAttribute(qkv_kernel,  cudaFuncAttributeMaxDynamicSharedMemorySize, QKV_SMEM);
    cudaFuncSetAttribute(attn_kernel, cudaFuncAttributeMaxDynamicSharedMemorySize, ATTN_SMEM);

    round_kernel<<<(2097152 + 196608) / 256, 256>>>(x, wq, wk, wv);
    qkv_kernel<<<dim3(128, 12), 256, QKV_SMEM>>>();
    attn_kernel<<<dim3(4, 256), 256, ATTN_SMEM>>>(btab);
    ln_kernel<<<Msz / 8, 256>>>(gamma, beta, (float*)d_out);
}